// round 1
// baseline (speedup 1.0000x reference)
#include <cuda_runtime.h>

#define D_MODEL   96
#define WIN       16
#define STRIDE    8
#define NHEAD     6
#define HEAD_DIM  16
#define INNER     96
#define FFN_H     192
#define L_SEQ     8192
#define NTHREADS  128

__global__ void zero_out_kernel(float* __restrict__ out, int n) {
    int i = blockIdx.x * blockDim.x + threadIdx.x;
    if (i < n) out[i] = 0.0f;
}

__device__ __forceinline__ float warp8_sum(float s) {
    s += __shfl_xor_sync(0xffffffffu, s, 1);
    s += __shfl_xor_sync(0xffffffffu, s, 2);
    s += __shfl_xor_sync(0xffffffffu, s, 4);
    return s;
}

// LayerNorm over 16 tokens x 96 dims. 128 threads = 16 tokens x 8 lanes.
__device__ __forceinline__ void ln16x96(const float* __restrict__ in,
                                        float* __restrict__ out,
                                        const float* __restrict__ g,
                                        const float* __restrict__ bb,
                                        int tid) {
    int token = tid >> 3;
    int lane  = tid & 7;
    const float* row = in + token * 96;
    float v[12];
    float s = 0.f;
#pragma unroll
    for (int i = 0; i < 12; i++) { v[i] = row[lane + 8 * i]; s += v[i]; }
    s = warp8_sum(s);
    float mean = s * (1.0f / 96.0f);
    float q = 0.f;
#pragma unroll
    for (int i = 0; i < 12; i++) { float d = v[i] - mean; q = fmaf(d, d, q); }
    q = warp8_sum(q);
    float rstd = rsqrtf(q * (1.0f / 96.0f) + 1e-5f);
    float* orow = out + token * 96;
#pragma unroll
    for (int i = 0; i < 12; i++) {
        int d = lane + 8 * i;
        orow[d] = (v[i] - mean) * rstd * g[d] + bb[d];
    }
}

__device__ __forceinline__ float gelu_tanh(float x) {
    float x3 = x * x * x;
    float inner = 0.7978845608028654f * fmaf(0.044715f, x3, x);
    return 0.5f * x * (1.0f + tanhf(inner));
}

// C(16xN) = A(16xK, smem) @ W(KxN, gmem) + bias. EPI: 0=store, 1=gelu-store, 2=residual add into R.
template <int N, int K, int EPI>
__device__ __forceinline__ void gemm16(const float* __restrict__ A,
                                       const float* __restrict__ W,
                                       const float* __restrict__ bias,
                                       float* __restrict__ C,
                                       float* __restrict__ R,
                                       int tid) {
    for (int j = tid; j < N; j += NTHREADS) {
        float acc[16];
        float bj = bias[j];
#pragma unroll
        for (int t = 0; t < 16; t++) acc[t] = bj;
        for (int k = 0; k < K; k += 4) {
            float w0 = W[(k + 0) * N + j];
            float w1 = W[(k + 1) * N + j];
            float w2 = W[(k + 2) * N + j];
            float w3 = W[(k + 3) * N + j];
#pragma unroll
            for (int t = 0; t < 16; t++) {
                float4 hv = *(const float4*)(A + t * K + k);
                acc[t] = fmaf(hv.x, w0, acc[t]);
                acc[t] = fmaf(hv.y, w1, acc[t]);
                acc[t] = fmaf(hv.z, w2, acc[t]);
                acc[t] = fmaf(hv.w, w3, acc[t]);
            }
        }
#pragma unroll
        for (int t = 0; t < 16; t++) {
            if (EPI == 0) {
                C[t * N + j] = acc[t];
            } else if (EPI == 1) {
                C[t * N + j] = gelu_tanh(acc[t]);
            } else {
                R[t * N + j] = R[t * N + j] + acc[t];
            }
        }
    }
}

__global__ void __launch_bounds__(NTHREADS)
win_block_kernel(const float* __restrict__ x,
                 const float* __restrict__ ln1_g, const float* __restrict__ ln1_b,
                 const float* __restrict__ qkv_w, const float* __restrict__ qkv_b,
                 const float* __restrict__ out_w, const float* __restrict__ out_b,
                 const float* __restrict__ ln2_g, const float* __restrict__ ln2_b,
                 const float* __restrict__ ffn_w1, const float* __restrict__ ffn_b1,
                 const float* __restrict__ ffn_w2, const float* __restrict__ ffn_b2,
                 const float* __restrict__ pln_g, const float* __restrict__ pln_b,
                 float* __restrict__ out) {
    __shared__ float s_x[WIN * 96];      // seg, later residual state
    __shared__ float s_a[WIN * 96];      // LN out / attn out / LN2 out / final
    __shared__ float s_qkv[WIN * 288];   // qkv; first 16x192 reused as ffn hidden

    const int tid = threadIdx.x;
    const int n = blockIdx.x;       // window index
    const int b = blockIdx.y;       // batch index

    const size_t base = ((size_t)b * L_SEQ + (size_t)n * STRIDE) * 96;

    // 1. gather seg (contiguous 16x96 block)
    {
        const float4* xin = (const float4*)(x + base);
        float4* dst = (float4*)s_x;
        for (int i = tid; i < (WIN * 96) / 4; i += NTHREADS) dst[i] = xin[i];
    }
    __syncthreads();

    // 2. LN1: s_x -> s_a
    ln16x96(s_x, s_a, ln1_g, ln1_b, tid);
    __syncthreads();

    // 3. qkv = h @ qkv_w + b : s_a(16x96) -> s_qkv(16x288)
    gemm16<288, 96, 0>(s_a, qkv_w, qkv_b, s_qkv, nullptr, tid);
    __syncthreads();

    // 4. causal attention per (head, qt); write o into s_a (16x96)
    if (tid < NHEAD * WIN) {
        const int h  = tid >> 4;     // head
        const int qt = tid & 15;     // query token
        const float* qrow = s_qkv + qt * 288 + h * HEAD_DIM;
        float qv[16];
#pragma unroll
        for (int d4 = 0; d4 < 4; d4++) {
            float4 t4 = *(const float4*)(qrow + d4 * 4);
            qv[d4 * 4 + 0] = t4.x; qv[d4 * 4 + 1] = t4.y;
            qv[d4 * 4 + 2] = t4.z; qv[d4 * 4 + 3] = t4.w;
        }
        float p[16];
        float mx = -1e30f;
#pragma unroll
        for (int kt = 0; kt < 16; kt++) {
            const float* krow = s_qkv + kt * 288 + 96 + h * HEAD_DIM;
            float sd = 0.f;
#pragma unroll
            for (int d4 = 0; d4 < 4; d4++) {
                float4 k4 = *(const float4*)(krow + d4 * 4);
                sd = fmaf(qv[d4 * 4 + 0], k4.x, sd);
                sd = fmaf(qv[d4 * 4 + 1], k4.y, sd);
                sd = fmaf(qv[d4 * 4 + 2], k4.z, sd);
                sd = fmaf(qv[d4 * 4 + 3], k4.w, sd);
            }
            sd *= 0.25f;                       // 1/sqrt(16)
            p[kt] = (kt <= qt) ? sd : -1e30f;  // causal mask
            mx = fmaxf(mx, p[kt]);
        }
        float denom = 0.f;
#pragma unroll
        for (int kt = 0; kt < 16; kt++) {
            p[kt] = __expf(p[kt] - mx);
            denom += p[kt];
        }
        float inv = 1.0f / denom;
        float ov[16];
#pragma unroll
        for (int d = 0; d < 16; d++) ov[d] = 0.f;
#pragma unroll
        for (int kt = 0; kt < 16; kt++) {
            const float* vrow = s_qkv + kt * 288 + 192 + h * HEAD_DIM;
#pragma unroll
            for (int d4 = 0; d4 < 4; d4++) {
                float4 v4 = *(const float4*)(vrow + d4 * 4);
                ov[d4 * 4 + 0] = fmaf(p[kt], v4.x, ov[d4 * 4 + 0]);
                ov[d4 * 4 + 1] = fmaf(p[kt], v4.y, ov[d4 * 4 + 1]);
                ov[d4 * 4 + 2] = fmaf(p[kt], v4.z, ov[d4 * 4 + 2]);
                ov[d4 * 4 + 3] = fmaf(p[kt], v4.w, ov[d4 * 4 + 3]);
            }
        }
        float* orow = s_a + qt * 96 + h * HEAD_DIM;
#pragma unroll
        for (int d = 0; d < 16; d++) orow[d] = ov[d] * inv;
    }
    __syncthreads();

    // 5. o @ out_w + out_b, add into residual s_x (seg + o)
    gemm16<96, 96, 2>(s_a, out_w, out_b, nullptr, s_x, tid);
    __syncthreads();

    // 6. LN2: s_x -> s_a
    ln16x96(s_x, s_a, ln2_g, ln2_b, tid);
    __syncthreads();

    // 7. FFN1 + gelu: s_a(16x96) @ w1(96x192) -> s_g (reuse s_qkv)
    float* s_g = s_qkv;
    gemm16<FFN_H, 96, 1>(s_a, ffn_w1, ffn_b1, s_g, nullptr, tid);
    __syncthreads();

    // 8. FFN2: s_g(16x192) @ w2(192x96), add into s_x
    gemm16<96, FFN_H, 2>(s_g, ffn_w2, ffn_b2, nullptr, s_x, tid);
    __syncthreads();

    // 9. final LN: s_x -> s_a
    ln16x96(s_x, s_a, pln_g, pln_b, tid);
    __syncthreads();

    // 10. scatter-add with analytic coverage count (2 interior, 1 at edges)
    for (int i = tid; i < WIN * 96; i += NTHREADS) {
        int t = i / 96;
        int pos = n * STRIDE + t;
        float invc = (pos < STRIDE || pos >= L_SEQ - STRIDE) ? 1.0f : 0.5f;
        atomicAdd(out + base + i, s_a[i] * invc);
    }
}

extern "C" void kernel_launch(void* const* d_in, const int* in_sizes, int n_in,
                              void* d_out, int out_size) {
    const float* x      = (const float*)d_in[0];
    const float* ln1_g  = (const float*)d_in[1];
    const float* ln1_b  = (const float*)d_in[2];
    const float* qkv_w  = (const float*)d_in[3];
    const float* qkv_b  = (const float*)d_in[4];
    const float* out_w  = (const float*)d_in[5];
    const float* out_b  = (const float*)d_in[6];
    const float* ln2_g  = (const float*)d_in[7];
    const float* ln2_b  = (const float*)d_in[8];
    const float* ffn_w1 = (const float*)d_in[9];
    const float* ffn_b1 = (const float*)d_in[10];
    const float* ffn_w2 = (const float*)d_in[11];
    const float* ffn_b2 = (const float*)d_in[12];
    const float* pln_g  = (const float*)d_in[13];
    const float* pln_b  = (const float*)d_in[14];
    float* out = (float*)d_out;

    const int B = in_sizes[0] / (L_SEQ * D_MODEL);
    const int num_win = 1 + (L_SEQ - WIN) / STRIDE;   // 1023

    zero_out_kernel<<<(out_size + 511) / 512, 512>>>(out, out_size);

    dim3 grid(num_win, B);
    win_block_kernel<<<grid, NTHREADS>>>(
        x, ln1_g, ln1_b, qkv_w, qkv_b, out_w, out_b,
        ln2_g, ln2_b, ffn_w1, ffn_b1, ffn_w2, ffn_b2,
        pln_g, pln_b, out);
}